// round 11
// baseline (speedup 1.0000x reference)
#include <cuda_runtime.h>

// TPLoss: pred [4096, 8192] f32, labels [4096, 8192] i32 (0/1)
// sigmoid p; TP_b = sum(p*l); with l in {0,1}:
//   1 - TP - TN = 1 - N + Sp + Sl - 2*TP
// out_b = TP / (1 - TP - TN);  loss = -mean(out_b)
//
// FINAL (R6/R10 winner). One row per 512-thread CTA, 4 CTA/SM @ 32 regs
// (full 64-warp residency), __ldcs streaming loads, single-MUFU sigmoid
// (tanh.approx), fused last-block final reduction. Runs at 6.2-6.3 TB/s
// (~79% of HBM spec) -- the measured practical ceiling for this
// two-stream read pattern; SM-side pipes all have large headroom.

#define B_ROWS 4096
#define N_COLS 8192
#define VEC (N_COLS / 4)        // 2048 float4 per row
#define THREADS 512
#define NWARP (THREADS / 32)    // 16

__device__ float        g_row_out[B_ROWS];
__device__ unsigned int g_done = 0;   // reset by last block each launch

// sigmoid via single MUFU: sigmoid(x) = 0.5*tanh(0.5*x) + 0.5
__device__ __forceinline__ float fast_sigmoid(float x) {
    float t;
    asm("tanh.approx.f32 %0, %1;" : "=f"(t) : "f"(x * 0.5f));
    return fmaf(t, 0.5f, 0.5f);
}

__global__ __launch_bounds__(THREADS, 4)   // force <=32 regs: 4 CTA/SM, 64 warps
void tploss_fused_kernel(const float4* __restrict__ pred,
                         const int4*  __restrict__ labels,
                         float* __restrict__ out) {
    const int b = blockIdx.x;
    const float4* p = pred   + (size_t)b * VEC;
    const int4*   l = labels + (size_t)b * VEC;

    float sp = 0.f;   // sum sigmoid
    float tp = 0.f;   // sum sigmoid * label
    int   cnt = 0;    // sum label

    // 2048 float4 / 512 threads = 4 iterations
    #pragma unroll 4
    for (int i = threadIdx.x; i < VEC; i += THREADS) {
        float4 x = __ldcs(&p[i]);   // streaming: no reuse
        int4   y = __ldcs(&l[i]);
        float s0 = fast_sigmoid(x.x);
        float s1 = fast_sigmoid(x.y);
        float s2 = fast_sigmoid(x.z);
        float s3 = fast_sigmoid(x.w);
        sp += (s0 + s1) + (s2 + s3);
        tp += (y.x ? s0 : 0.f) + (y.y ? s1 : 0.f)
            + (y.z ? s2 : 0.f) + (y.w ? s3 : 0.f);
        cnt += y.x + y.y + y.z + y.w;
    }

    // warp reduce 3 accumulators
    #pragma unroll
    for (int off = 16; off > 0; off >>= 1) {
        sp  += __shfl_down_sync(0xffffffffu, sp,  off);
        tp  += __shfl_down_sync(0xffffffffu, tp,  off);
        cnt += __shfl_down_sync(0xffffffffu, cnt, off);
    }

    __shared__ float s_sp[NWARP];
    __shared__ float s_tp[NWARP];
    __shared__ int   s_cnt[NWARP];
    const int lane = threadIdx.x & 31;
    const int wid  = threadIdx.x >> 5;
    if (lane == 0) { s_sp[wid] = sp; s_tp[wid] = tp; s_cnt[wid] = cnt; }
    __syncthreads();

    __shared__ bool s_is_last;
    if (threadIdx.x == 0) {
        float fsp = 0.f, ftp = 0.f; int fc = 0;
        #pragma unroll
        for (int w = 0; w < NWARP; w++) {
            fsp += s_sp[w]; ftp += s_tp[w]; fc += s_cnt[w];
        }
        float denom = 1.0f - (float)N_COLS + fsp + (float)fc - 2.0f * ftp;
        g_row_out[b] = ftp / denom;
        __threadfence();
        unsigned int prev = atomicAdd(&g_done, 1u);
        s_is_last = (prev == (unsigned int)(gridDim.x - 1));
    }
    __syncthreads();

    if (s_is_last) {
        __threadfence();  // acquire: all g_row_out writes visible
        // 4096 rows / 512 threads = 8 per thread, deterministic order
        float acc = 0.f;
        #pragma unroll 8
        for (int i = threadIdx.x; i < B_ROWS; i += THREADS)
            acc += g_row_out[i];

        #pragma unroll
        for (int off = 16; off > 0; off >>= 1)
            acc += __shfl_down_sync(0xffffffffu, acc, off);

        __shared__ float s_fin[NWARP];
        if (lane == 0) s_fin[wid] = acc;
        __syncthreads();
        if (threadIdx.x == 0) {
            float tot = 0.f;
            #pragma unroll
            for (int w = 0; w < NWARP; w++) tot += s_fin[w];
            out[0] = -tot / (float)B_ROWS;
            g_done = 0;   // reset for next graph replay
        }
    }
}

extern "C" void kernel_launch(void* const* d_in, const int* in_sizes, int n_in,
                              void* d_out, int out_size) {
    const float4* pred   = (const float4*)d_in[0];
    const int4*   labels = (const int4*)d_in[1];
    float* out = (float*)d_out;

    tploss_fused_kernel<<<B_ROWS, THREADS>>>(pred, labels, out);
}

// round 12
// speedup vs baseline: 1.0056x; 1.0056x over previous
#include <cuda_runtime.h>

// TPLoss: pred [4096, 8192] f32, labels [4096, 8192] i32 (0/1)
// sigmoid p; TP_b = sum(p*l); with l in {0,1}:
//   1 - TP - TN = 1 - N + Sp + Sl - 2*TP
// out_b = TP / (1 - TP - TN);  loss = -mean(out_b)
// R6 winner shape (512 threads/CTA, one row/CTA, 4 CTA/SM @ 32 regs) with
// ONE change: 256-bit LDG (ld.global.cs.v8.b32, sm_100a+) -- halves LSU
// queue slots per byte, doubling in-flight bytes per scoreboard slot.

#define B_ROWS 4096
#define N_COLS 8192
#define VEC8 (N_COLS / 8)       // 1024 x 32B per row
#define THREADS 512
#define NWARP (THREADS / 32)    // 16

__device__ float        g_row_out[B_ROWS];
__device__ unsigned int g_done = 0;   // reset by last block each launch

// sigmoid via single MUFU: sigmoid(x) = 0.5*tanh(0.5*x) + 0.5
__device__ __forceinline__ float fast_sigmoid(float x) {
    float t;
    asm("tanh.approx.f32 %0, %1;" : "=f"(t) : "f"(x * 0.5f));
    return fmaf(t, 0.5f, 0.5f);
}

struct V8 { unsigned int r[8]; };

// 256-bit streaming global load (Blackwell sm_100a+)
__device__ __forceinline__ V8 ldg256_cs(const void* p) {
    V8 v;
    asm("ld.global.cs.v8.b32 {%0,%1,%2,%3,%4,%5,%6,%7}, [%8];"
        : "=r"(v.r[0]), "=r"(v.r[1]), "=r"(v.r[2]), "=r"(v.r[3]),
          "=r"(v.r[4]), "=r"(v.r[5]), "=r"(v.r[6]), "=r"(v.r[7])
        : "l"(p));
    return v;
}

__global__ __launch_bounds__(THREADS, 4)   // force <=32 regs: 4 CTA/SM, 64 warps
void tploss_fused_kernel(const float* __restrict__ pred,
                         const int*  __restrict__ labels,
                         float* __restrict__ out) {
    const int b = blockIdx.x;
    const float* p = pred   + (size_t)b * N_COLS;
    const int*   l = labels + (size_t)b * N_COLS;

    float sp = 0.f;   // sum sigmoid
    float tp = 0.f;   // sum sigmoid * label
    int   cnt = 0;    // sum label

    // 1024 x 32B / 512 threads = 2 iterations
    #pragma unroll 2
    for (int i = threadIdx.x; i < VEC8; i += THREADS) {
        V8 x = ldg256_cs(p + (size_t)i * 8);
        V8 y = ldg256_cs(l + (size_t)i * 8);
        #pragma unroll
        for (int j = 0; j < 8; j++) {
            float s = fast_sigmoid(__uint_as_float(x.r[j]));
            sp += s;
            tp += (y.r[j] ? s : 0.f);
            cnt += (int)y.r[j];
        }
    }

    // warp reduce 3 accumulators
    #pragma unroll
    for (int off = 16; off > 0; off >>= 1) {
        sp  += __shfl_down_sync(0xffffffffu, sp,  off);
        tp  += __shfl_down_sync(0xffffffffu, tp,  off);
        cnt += __shfl_down_sync(0xffffffffu, cnt, off);
    }

    __shared__ float s_sp[NWARP];
    __shared__ float s_tp[NWARP];
    __shared__ int   s_cnt[NWARP];
    const int lane = threadIdx.x & 31;
    const int wid  = threadIdx.x >> 5;
    if (lane == 0) { s_sp[wid] = sp; s_tp[wid] = tp; s_cnt[wid] = cnt; }
    __syncthreads();

    __shared__ bool s_is_last;
    if (threadIdx.x == 0) {
        float fsp = 0.f, ftp = 0.f; int fc = 0;
        #pragma unroll
        for (int w = 0; w < NWARP; w++) {
            fsp += s_sp[w]; ftp += s_tp[w]; fc += s_cnt[w];
        }
        float denom = 1.0f - (float)N_COLS + fsp + (float)fc - 2.0f * ftp;
        g_row_out[b] = ftp / denom;
        __threadfence();
        unsigned int prev = atomicAdd(&g_done, 1u);
        s_is_last = (prev == (unsigned int)(gridDim.x - 1));
    }
    __syncthreads();

    if (s_is_last) {
        __threadfence();  // acquire: all g_row_out writes visible
        // 4096 rows / 512 threads = 8 per thread, deterministic order
        float acc = 0.f;
        #pragma unroll 8
        for (int i = threadIdx.x; i < B_ROWS; i += THREADS)
            acc += g_row_out[i];

        #pragma unroll
        for (int off = 16; off > 0; off >>= 1)
            acc += __shfl_down_sync(0xffffffffu, acc, off);

        __shared__ float s_fin[NWARP];
        if (lane == 0) s_fin[wid] = acc;
        __syncthreads();
        if (threadIdx.x == 0) {
            float tot = 0.f;
            #pragma unroll
            for (int w = 0; w < NWARP; w++) tot += s_fin[w];
            out[0] = -tot / (float)B_ROWS;
            g_done = 0;   // reset for next graph replay
        }
    }
}

extern "C" void kernel_launch(void* const* d_in, const int* in_sizes, int n_in,
                              void* d_out, int out_size) {
    const float* pred   = (const float*)d_in[0];
    const int*   labels = (const int*)d_in[1];
    float* out = (float*)d_out;

    tploss_fused_kernel<<<B_ROWS, THREADS>>>(pred, labels, out);
}

// round 13
// speedup vs baseline: 1.0529x; 1.0471x over previous
#include <cuda_runtime.h>

// TPLoss: pred [4096, 8192] f32, labels [4096, 8192] i32 (0/1)
// sigmoid p; TP_b = sum(p*l); with l in {0,1}:
//   1 - TP - TN = 1 - N + Sp + Sl - 2*TP
// out_b = TP / (1 - TP - TN);  loss = -mean(out_b)
//
// FINAL (R6 winner, session-best 44.9us). One row per 512-thread CTA,
// 4 CTA/SM @ 32 regs (full 64-warp residency), __ldcs streaming float4
// loads, single-MUFU sigmoid (tanh.approx), fused last-block final
// reduction. Pinned at ~6.2 TB/s (~78% HBM spec) -- verified to be the
// memory-path ceiling for this pattern: load width (128b/256b), cache
// op (cs/cg), block shape (256/512/1024), pipelining, persistent CTAs,
// and accumulator count all plateau at the same bandwidth.

#define B_ROWS 4096
#define N_COLS 8192
#define VEC (N_COLS / 4)        // 2048 float4 per row
#define THREADS 512
#define NWARP (THREADS / 32)    // 16

__device__ float        g_row_out[B_ROWS];
__device__ unsigned int g_done = 0;   // reset by last block each launch

// sigmoid via single MUFU: sigmoid(x) = 0.5*tanh(0.5*x) + 0.5
__device__ __forceinline__ float fast_sigmoid(float x) {
    float t;
    asm("tanh.approx.f32 %0, %1;" : "=f"(t) : "f"(x * 0.5f));
    return fmaf(t, 0.5f, 0.5f);
}

__global__ __launch_bounds__(THREADS, 4)   // force <=32 regs: 4 CTA/SM, 64 warps
void tploss_fused_kernel(const float4* __restrict__ pred,
                         const int4*  __restrict__ labels,
                         float* __restrict__ out) {
    const int b = blockIdx.x;
    const float4* p = pred   + (size_t)b * VEC;
    const int4*   l = labels + (size_t)b * VEC;

    float sp = 0.f;   // sum sigmoid
    float tp = 0.f;   // sum sigmoid * label
    int   cnt = 0;    // sum label

    // 2048 float4 / 512 threads = 4 iterations
    #pragma unroll 4
    for (int i = threadIdx.x; i < VEC; i += THREADS) {
        float4 x = __ldcs(&p[i]);   // streaming: no reuse
        int4   y = __ldcs(&l[i]);
        float s0 = fast_sigmoid(x.x);
        float s1 = fast_sigmoid(x.y);
        float s2 = fast_sigmoid(x.z);
        float s3 = fast_sigmoid(x.w);
        sp += (s0 + s1) + (s2 + s3);
        tp += (y.x ? s0 : 0.f) + (y.y ? s1 : 0.f)
            + (y.z ? s2 : 0.f) + (y.w ? s3 : 0.f);
        cnt += y.x + y.y + y.z + y.w;
    }

    // warp reduce 3 accumulators
    #pragma unroll
    for (int off = 16; off > 0; off >>= 1) {
        sp  += __shfl_down_sync(0xffffffffu, sp,  off);
        tp  += __shfl_down_sync(0xffffffffu, tp,  off);
        cnt += __shfl_down_sync(0xffffffffu, cnt, off);
    }

    __shared__ float s_sp[NWARP];
    __shared__ float s_tp[NWARP];
    __shared__ int   s_cnt[NWARP];
    const int lane = threadIdx.x & 31;
    const int wid  = threadIdx.x >> 5;
    if (lane == 0) { s_sp[wid] = sp; s_tp[wid] = tp; s_cnt[wid] = cnt; }
    __syncthreads();

    __shared__ bool s_is_last;
    if (threadIdx.x == 0) {
        float fsp = 0.f, ftp = 0.f; int fc = 0;
        #pragma unroll
        for (int w = 0; w < NWARP; w++) {
            fsp += s_sp[w]; ftp += s_tp[w]; fc += s_cnt[w];
        }
        float denom = 1.0f - (float)N_COLS + fsp + (float)fc - 2.0f * ftp;
        g_row_out[b] = ftp / denom;
        __threadfence();
        unsigned int prev = atomicAdd(&g_done, 1u);
        s_is_last = (prev == (unsigned int)(gridDim.x - 1));
    }
    __syncthreads();

    if (s_is_last) {
        __threadfence();  // acquire: all g_row_out writes visible
        // 4096 rows / 512 threads = 8 per thread, deterministic order
        float acc = 0.f;
        #pragma unroll 8
        for (int i = threadIdx.x; i < B_ROWS; i += THREADS)
            acc += g_row_out[i];

        #pragma unroll
        for (int off = 16; off > 0; off >>= 1)
            acc += __shfl_down_sync(0xffffffffu, acc, off);

        __shared__ float s_fin[NWARP];
        if (lane == 0) s_fin[wid] = acc;
        __syncthreads();
        if (threadIdx.x == 0) {
            float tot = 0.f;
            #pragma unroll
            for (int w = 0; w < NWARP; w++) tot += s_fin[w];
            out[0] = -tot / (float)B_ROWS;
            g_done = 0;   // reset for next graph replay
        }
    }
}

extern "C" void kernel_launch(void* const* d_in, const int* in_sizes, int n_in,
                              void* d_out, int out_size) {
    const float4* pred   = (const float4*)d_in[0];
    const int4*   labels = (const int4*)d_in[1];
    float* out = (float*)d_out;

    tploss_fused_kernel<<<B_ROWS, THREADS>>>(pred, labels, out);
}